// round 4
// baseline (speedup 1.0000x reference)
#include <cuda_runtime.h>
#include <cstdint>

#define NN 500
#define GG 128
#define HH 200
#define WW 304
#define HWPX (HH * WW)            // 60800
#define WORDS 1900                // HWPX/32 exact
#define WSTRIDE 1920              // padded bit-row stride (u32), 16B multiple
#define MAXPAIRS (NN * (NN - 1) / 2)
#define MASK_THR 0.005f
#define SIGMA 2.0f

#define SWORDS 3                  // words per strip
#define SPX (SWORDS * 32)         // 96 px per strip
#define NSTRIPS ((WORDS + SWORDS - 1) / SWORDS)   // 634 (last strip = 1 word)
#define NSTRIPS_PAD 640
#define DEC_THREADS 512
// smem: 256 rows * 96 px * 4B + 2*500 ints
#define DEC_SMEM (256 * SPX * 4 + 2 * NN * 4)

// ---- device scratch (zero-init at load; resets maintained per replay) ----
__device__ __align__(16) unsigned int g_bits[NN * WSTRIDE];
__device__ int   g_area[NN];                       // int atomics: deterministic
__device__ float g_part[NN * NSTRIPS_PAD];         // per-(mask,strip) soft sums; pad cols stay 0
__device__ float g_comp[NN];
__device__ int   g_npairs;
__device__ unsigned int g_pair_ij[MAXPAIRS];
__device__ float g_pair_d[MAXPAIRS];

// ============================================================
// Kernel 1: strip-stationary decode. CTA = 96-px strip; smem holds
// that strip of ALL 256 grid rows; warps stream the 500 masks.
// ============================================================
__global__ __launch_bounds__(DEC_THREADS) void decode_kernel(
    const float* __restrict__ segx,
    const float* __restrict__ segy,
    const int* __restrict__ x_inds,
    const int* __restrict__ y_inds)
{
    extern __shared__ float smem[];
    float* sx = smem;                      // [128][SPX]
    float* sy = smem + GG * SPX;           // [128][SPX]
    int*   sxi = (int*)(smem + 2 * GG * SPX);
    int*   syi = sxi + NN;

    const int strip = blockIdx.x;
    const int tid = threadIdx.x;
    const int base_px = strip * SPX;
    const int sw = min(SWORDS, WORDS - strip * SWORDS);   // 3, or 1 on last strip
    const int nf4 = sw * 8;                               // float4 per row

    for (int k = tid; k < NN; k += DEC_THREADS) { sxi[k] = x_inds[k]; syi[k] = y_inds[k]; }

    for (int idx = tid; idx < GG * nf4; idx += DEC_THREADS) {
        const int row = idx / nf4;
        const int col = idx - row * nf4;
        const size_t goff = (size_t)row * HWPX + base_px + col * 4;
        *reinterpret_cast<float4*>(sx + row * SPX + col * 4) =
            *reinterpret_cast<const float4*>(segx + goff);
        *reinterpret_cast<float4*>(sy + row * SPX + col * 4) =
            *reinterpret_cast<const float4*>(segy + goff);
    }
    __syncthreads();

    const int warp = tid >> 5;
    const int lane = tid & 31;

    for (int n = warp; n < NN; n += DEC_THREADS / 32) {
        const float* __restrict__ rx = sx + sxi[n] * SPX;
        const float* __restrict__ ry = sy + syi[n] * SPX;
        float ssum = 0.0f;
        int   area = 0;
#pragma unroll
        for (int c = 0; c < SWORDS; c++) {
            if (c >= sw) break;
            const float s = rx[c * 32 + lane] * ry[c * 32 + lane];
            const bool pr = (s > MASK_THR);
            const unsigned wbits = __ballot_sync(0xffffffffu, pr);
            if (pr) ssum += s;
            if (lane == 0) {
                g_bits[n * WSTRIDE + strip * SWORDS + c] = wbits;
                area += __popc(wbits);
            }
        }
#pragma unroll
        for (int off = 16; off > 0; off >>= 1)
            ssum += __shfl_down_sync(0xffffffffu, ssum, off);
        if (lane == 0) {
            g_part[n * NSTRIPS_PAD + strip] = ssum;
            atomicAdd(&g_area[n], area);
        }
    }
}

// ============================================================
// Kernel 2: compact same-label pair list + comp init
// ============================================================
__global__ __launch_bounds__(256) void pairbuild_kernel(const int* __restrict__ labels)
{
    const int i = blockIdx.x;
    const int tid = threadIdx.x;
    const int lab = labels[i];
    if (tid == 0) g_comp[i] = 0.0f;
    for (int j = i + 1 + tid; j < NN; j += 256) {
        if (labels[j] == lab) {
            int pos = atomicAdd(&g_npairs, 1);
            g_pair_ij[pos] = ((unsigned)i << 16) | (unsigned)j;
        }
    }
}

// ============================================================
// Kernel 3: pair popcount intersections (one warp per pair)
// ============================================================
__global__ __launch_bounds__(256) void popc_kernel()
{
    const int lane  = threadIdx.x & 31;
    const int gwarp = (blockIdx.x * 256 + threadIdx.x) >> 5;
    const int NW    = gridDim.x * 8;
    const int np    = g_npairs;

    for (int p = gwarp; p < np; p += NW) {
        const unsigned ij = g_pair_ij[p];
        const int i = (int)(ij >> 16);
        const int j = (int)(ij & 0xffffu);

        const uint4* __restrict__ bi = reinterpret_cast<const uint4*>(g_bits + i * WSTRIDE);
        const uint4* __restrict__ bj = reinterpret_cast<const uint4*>(g_bits + j * WSTRIDE);

        int inter = 0;
#pragma unroll 5
        for (int w = lane; w < WSTRIDE / 4; w += 32) {
            uint4 a = bi[w];
            uint4 b = bj[w];
            inter += __popc(a.x & b.x) + __popc(a.y & b.y)
                   + __popc(a.z & b.z) + __popc(a.w & b.w);
        }
#pragma unroll
        for (int off = 16; off > 0; off >>= 1)
            inter += __shfl_down_sync(0xffffffffu, inter, off);

        if (lane == 0) {
            float uni = (float)(g_area[i] + g_area[j] - inter);
            float iou = (float)inter / fmaxf(uni, 1e-6f);
            g_pair_d[p] = iou;
            atomicMax(reinterpret_cast<int*>(&g_comp[j]), __float_as_int(iou)); // iou>=0
        }
    }
}

// ============================================================
// Kernel 4 (single block): reduce soft sums -> scores; decay -> smem
// coef min; final output; reset accumulators for next replay.
// ============================================================
__global__ __launch_bounds__(1024) void decayfinal_kernel(
    const float* __restrict__ cate_scores,
    float* __restrict__ out)
{
    __shared__ float s_coef[NN];
    __shared__ float s_score[NN];
    const int tid = threadIdx.x;
    const int warp = tid >> 5;
    const int lane = tid & 31;

    // phase 1: fixed-order reduce of per-strip soft sums (pad cols are 0)
    for (int n = warp; n < NN; n += 32) {
        float acc = 0.0f;
#pragma unroll
        for (int k = 0; k < NSTRIPS_PAD / 32; k++)
            acc += g_part[n * NSTRIPS_PAD + k * 32 + lane];
#pragma unroll
        for (int off = 16; off > 0; off >>= 1)
            acc += __shfl_down_sync(0xffffffffu, acc, off);
        if (lane == 0) {
            float area = (float)g_area[n];
            s_score[n] = cate_scores[n] * (acc / fmaxf(area, 1.0f));
            s_coef[n] = 1.0f;
            g_area[n] = 0;                  // reset for next replay
        }
    }
    __syncthreads();

    // phase 2: decay terms -> order-independent min into smem coef
    const int np = g_npairs;
    for (int p = tid; p < np; p += 1024) {
        const unsigned ij = g_pair_ij[p];
        const int i = (int)(ij >> 16);
        const int j = (int)(ij & 0xffffu);
        const float d = g_pair_d[p];
        const float c = g_comp[i];
        const float term = __expf(SIGMA * (c * c - d * d));   // > 0
        atomicMin(reinterpret_cast<int*>(&s_coef[j]), __float_as_int(term));
    }
    __syncthreads();

    // phase 3: output
    for (int n = tid; n < NN; n += 1024)
        out[n] = s_score[n] * fminf(s_coef[n], 1.0f);
    if (tid == 0) g_npairs = 0;            // reset for next replay
}

extern "C" void kernel_launch(void* const* d_in, const int* in_sizes, int n_in,
                              void* d_out, int out_size)
{
    const float* cate_scores = (const float*)d_in[0];
    const float* segx        = (const float*)d_in[1];
    const float* segy        = (const float*)d_in[2];
    const int*   labels      = (const int*)d_in[3];
    const int*   x_inds      = (const int*)d_in[4];
    const int*   y_inds      = (const int*)d_in[5];
    float* out = (float*)d_out;

    static int smem_set = 0;
    if (!smem_set) {
        cudaFuncSetAttribute(decode_kernel,
                             cudaFuncAttributeMaxDynamicSharedMemorySize, DEC_SMEM);
        smem_set = 1;
    }

    decode_kernel<<<NSTRIPS, DEC_THREADS, DEC_SMEM>>>(segx, segy, x_inds, y_inds);
    pairbuild_kernel<<<NN, 256>>>(labels);
    popc_kernel<<<208, 256>>>();
    decayfinal_kernel<<<1, 1024>>>(cate_scores, out);
}

// round 5
// speedup vs baseline: 1.2886x; 1.2886x over previous
#include <cuda_runtime.h>
#include <cstdint>

#define NN 500
#define GG 128
#define HH 200
#define WW 304
#define HWPX (HH * WW)            // 60800
#define WORDS 1900                // HWPX/32 exact
#define WSTRIDE 1920              // padded bit-row stride (u32), 16B multiple
#define MAXPAIRS (NN * (NN - 1) / 2)
#define MASK_THR 0.005f
#define SIGMA 2.0f

#define NCHUNK 8                  // chunks per mask
#define CHUNKW 240                // words per chunk (last chunk: 220)

// ---- device scratch (zero-init at load; decayfinal resets per replay) ----
__device__ __align__(16) unsigned int g_bits[NN * WSTRIDE];
__device__ int   g_area[NN];              // int atomics: deterministic
__device__ float g_part8[NN * NCHUNK];    // per-(mask,chunk) soft sums, single writer
__device__ float g_comp[NN];              // comp_iou (0 at entry)
__device__ int   g_npairs;                // 0 at entry
__device__ unsigned int g_pair_ij[MAXPAIRS];
__device__ float g_pair_d[MAXPAIRS];

// ============================================================
// Kernel 1: decode. 8 CTAs per mask (blockIdx.x = mask*8 + chunk).
// ============================================================
__global__ __launch_bounds__(256) void decode_kernel(
    const float* __restrict__ segx,
    const float* __restrict__ segy,
    const int* __restrict__ x_inds,
    const int* __restrict__ y_inds)
{
    const int n   = blockIdx.x >> 3;
    const int c   = blockIdx.x & 7;
    const int tid = threadIdx.x;

    const int xi = x_inds[n];
    const int yi = y_inds[n];
    const float4* __restrict__ rx = reinterpret_cast<const float4*>(segx + (size_t)xi * HWPX);
    const float4* __restrict__ ry = reinterpret_cast<const float4*>(segy + (size_t)yi * HWPX);

    const int w0 = c * CHUNKW;
    const int w1 = (c == NCHUNK - 1) ? WORDS : (w0 + CHUNKW);

    int   area = 0;
    float ssum = 0.0f;

    // word w covers pixels [32w,32w+32) = float4 indices [8w,8w+8)
    for (int w = w0 + tid; w < w1; w += 256) {
        unsigned int bits = 0;
        const int f4 = w * 8;
#pragma unroll
        for (int q = 0; q < 8; q++) {
            float4 a = rx[f4 + q];
            float4 b = ry[f4 + q];
            float s0 = a.x * b.x;
            float s1 = a.y * b.y;
            float s2 = a.z * b.z;
            float s3 = a.w * b.w;
            if (s0 > MASK_THR) { bits |= 1u << (q * 4 + 0); ssum += s0; }
            if (s1 > MASK_THR) { bits |= 1u << (q * 4 + 1); ssum += s1; }
            if (s2 > MASK_THR) { bits |= 1u << (q * 4 + 2); ssum += s2; }
            if (s3 > MASK_THR) { bits |= 1u << (q * 4 + 3); ssum += s3; }
        }
        g_bits[n * WSTRIDE + w] = bits;
        area += __popc(bits);
    }
    // last chunk also zeroes the pad words [1900,1920)
    if (c == NCHUNK - 1 && tid < WSTRIDE - WORDS)
        g_bits[n * WSTRIDE + WORDS + tid] = 0u;

    // block reduction (8 warps)
    __shared__ float s_sum[8];
    __shared__ int   s_area[8];
#pragma unroll
    for (int off = 16; off > 0; off >>= 1) {
        ssum += __shfl_down_sync(0xffffffffu, ssum, off);
        area += __shfl_down_sync(0xffffffffu, area, off);
    }
    if ((tid & 31) == 0) { s_sum[tid >> 5] = ssum; s_area[tid >> 5] = area; }
    __syncthreads();
    if (tid == 0) {
        float tsum = 0.0f; int tarea = 0;
#pragma unroll
        for (int k = 0; k < 8; k++) { tsum += s_sum[k]; tarea += s_area[k]; }
        g_part8[n * NCHUNK + c] = tsum;        // single writer: deterministic
        atomicAdd(&g_area[n], tarea);          // int atomic: deterministic
    }
}

// ============================================================
// Kernel 2: fused pair enumeration + popcount intersection.
// Grid-stride warps over all (i,j) cells; cheap smem label gate.
// ============================================================
__global__ __launch_bounds__(256) void popc_kernel(const int* __restrict__ labels)
{
    __shared__ int s_lab[NN];
    const int tid  = threadIdx.x;
    const int lane = tid & 31;
    const int gwarp = (blockIdx.x * 256 + tid) >> 5;
    const int NW = gridDim.x * 8;

    for (int k = tid; k < NN; k += 256) s_lab[k] = labels[k];
    __syncthreads();

    for (int p = gwarp; p < NN * NN; p += NW) {
        const int i = p / NN;
        const int j = p - i * NN;
        if (j <= i) continue;
        if (s_lab[i] != s_lab[j]) continue;

        const uint4* __restrict__ bi = reinterpret_cast<const uint4*>(g_bits + i * WSTRIDE);
        const uint4* __restrict__ bj = reinterpret_cast<const uint4*>(g_bits + j * WSTRIDE);

        int inter = 0;
#pragma unroll 5
        for (int w = lane; w < WSTRIDE / 4; w += 32) {   // 15 iterations
            uint4 a = bi[w];
            uint4 b = bj[w];
            inter += __popc(a.x & b.x) + __popc(a.y & b.y)
                   + __popc(a.z & b.z) + __popc(a.w & b.w);
        }
#pragma unroll
        for (int off = 16; off > 0; off >>= 1)
            inter += __shfl_down_sync(0xffffffffu, inter, off);

        if (lane == 0) {
            float uni = (float)(g_area[i] + g_area[j] - inter);
            float iou = (float)inter / fmaxf(uni, 1e-6f);
            atomicMax(reinterpret_cast<int*>(&g_comp[j]), __float_as_int(iou)); // iou>=0
            int pos = atomicAdd(&g_npairs, 1);
            g_pair_ij[pos] = ((unsigned)i << 16) | (unsigned)j;
            g_pair_d[pos] = iou;
        }
    }
}

// ============================================================
// Kernel 3 (single block, tiny data): scores + decay + output + reset.
// ============================================================
__global__ __launch_bounds__(1024) void decayfinal_kernel(
    const float* __restrict__ cate_scores,
    float* __restrict__ out)
{
    __shared__ float s_coef[NN];
    __shared__ float s_score[NN];
    const int tid = threadIdx.x;

    // phase 1: fixed-order reduce of 8 chunk partials per mask
    for (int n = tid; n < NN; n += 1024) {
        float acc = 0.0f;
#pragma unroll
        for (int k = 0; k < NCHUNK; k++) acc += g_part8[n * NCHUNK + k];
        float area = (float)g_area[n];
        s_score[n] = cate_scores[n] * (acc / fmaxf(area, 1.0f));
        s_coef[n] = 1.0f;
    }
    __syncthreads();

    // phase 2: decay terms -> order-independent min into smem coef
    const int np = g_npairs;
    for (int p = tid; p < np; p += 1024) {
        const unsigned ij = g_pair_ij[p];
        const int i = (int)(ij >> 16);
        const int j = (int)(ij & 0xffffu);
        const float d = g_pair_d[p];
        const float c = g_comp[i];
        const float term = __expf(SIGMA * (c * c - d * d));   // > 0
        atomicMin(reinterpret_cast<int*>(&s_coef[j]), __float_as_int(term));
    }
    __syncthreads();

    // phase 3: output + reset accumulators for next replay
    for (int n = tid; n < NN; n += 1024) {
        out[n] = s_score[n] * fminf(s_coef[n], 1.0f);
        g_area[n] = 0;
        g_comp[n] = 0.0f;
    }
    if (tid == 0) g_npairs = 0;
}

extern "C" void kernel_launch(void* const* d_in, const int* in_sizes, int n_in,
                              void* d_out, int out_size)
{
    const float* cate_scores = (const float*)d_in[0];
    const float* segx        = (const float*)d_in[1];
    const float* segy        = (const float*)d_in[2];
    const int*   labels      = (const int*)d_in[3];
    const int*   x_inds      = (const int*)d_in[4];
    const int*   y_inds      = (const int*)d_in[5];
    float* out = (float*)d_out;

    decode_kernel<<<NN * NCHUNK, 256>>>(segx, segy, x_inds, y_inds);
    popc_kernel<<<304, 256>>>(labels);
    decayfinal_kernel<<<1, 1024>>>(cate_scores, out);
}

// round 6
// speedup vs baseline: 2.1052x; 1.6337x over previous
#include <cuda_runtime.h>
#include <cstdint>

#define NN 500
#define GG 128
#define HH 200
#define WW 304
#define HWPX (HH * WW)            // 60800
#define WORDS 1900                // HWPX/32 exact
#define WSTRIDE 1920              // padded bit-row stride (u32), 16B multiple
#define MAXPAIRS (NN * (NN - 1) / 2)
#define MASK_THR 0.005f
#define SIGMA 2.0f

#define NCHUNK 8                  // chunks per mask
#define CHUNKW 240                // words per chunk (last chunk: 220). multiples of 4.

// ---- device scratch (zero-init at load; decayfinal resets per replay) ----
__device__ __align__(16) unsigned int g_bits[NN * WSTRIDE];
__device__ int   g_area[NN];              // int atomics: deterministic
__device__ float g_part8[NN * NCHUNK];    // per-(mask,chunk) soft sums, single writer
__device__ float g_comp[NN];              // comp_iou (0 at entry)
__device__ int   g_npairs;                // 0 at entry
__device__ unsigned int g_pair_ij[MAXPAIRS];
__device__ float g_pair_d[MAXPAIRS];

// ============================================================
// Kernel 1: decode, warp-coalesced. Each warp iteration covers 128
// consecutive pixels: lane L loads float4 #L -> 2 contiguous 512B
// reads. Hard-mask bits are packed in ballot order (a fixed pixel
// permutation -- invariant for popc/AND/area/sums).
// blockIdx.x = mask*8 + chunk.
// ============================================================
__global__ __launch_bounds__(256) void decode_kernel(
    const float* __restrict__ segx,
    const float* __restrict__ segy,
    const int* __restrict__ x_inds,
    const int* __restrict__ y_inds)
{
    const int n   = blockIdx.x >> 3;
    const int c   = blockIdx.x & 7;
    const int tid = threadIdx.x;
    const int warp = tid >> 5;
    const int lane = tid & 31;

    const int xi = x_inds[n];
    const int yi = y_inds[n];
    const float4* __restrict__ rx = reinterpret_cast<const float4*>(segx + (size_t)xi * HWPX);
    const float4* __restrict__ ry = reinterpret_cast<const float4*>(segy + (size_t)yi * HWPX);

    const int w0 = c * CHUNKW;                                    // word base
    const int nquads = ((c == NCHUNK - 1) ? (WORDS - w0) : CHUNKW) >> 2;  // 60 or 55

    float ssum = 0.0f;
    int   area = 0;

    // quad k covers words [w0+4k, w0+4k+4) = pixels [(w0+4k)*32, +128)
    for (int k = warp; k < nquads; k += 8) {
        const int f4 = (w0 + 4 * k) * 8 + lane;   // 32 consecutive float4 per warp
        float4 a = rx[f4];
        float4 b = ry[f4];
        const float s0 = a.x * b.x;
        const float s1 = a.y * b.y;
        const float s2 = a.z * b.z;
        const float s3 = a.w * b.w;
        const bool p0 = s0 > MASK_THR;
        const bool p1 = s1 > MASK_THR;
        const bool p2 = s2 > MASK_THR;
        const bool p3 = s3 > MASK_THR;
        const unsigned b0 = __ballot_sync(0xffffffffu, p0);
        const unsigned b1 = __ballot_sync(0xffffffffu, p1);
        const unsigned b2 = __ballot_sync(0xffffffffu, p2);
        const unsigned b3 = __ballot_sync(0xffffffffu, p3);
        if (p0) ssum += s0;
        if (p1) ssum += s1;
        if (p2) ssum += s2;
        if (p3) ssum += s3;
        if (lane < 4) {
            const unsigned wb = (lane == 0) ? b0 : (lane == 1) ? b1 : (lane == 2) ? b2 : b3;
            g_bits[n * WSTRIDE + w0 + 4 * k + lane] = wb;
        }
        if (lane == 0)
            area += __popc(b0) + __popc(b1) + __popc(b2) + __popc(b3);
    }
    // last chunk zeroes the pad words [1900,1920)
    if (c == NCHUNK - 1 && tid < WSTRIDE - WORDS)
        g_bits[n * WSTRIDE + WORDS + tid] = 0u;

    // block reduction (8 warps)
    __shared__ float s_sum[8];
    __shared__ int   s_area[8];
#pragma unroll
    for (int off = 16; off > 0; off >>= 1)
        ssum += __shfl_down_sync(0xffffffffu, ssum, off);
    if (lane == 0) { s_sum[warp] = ssum; s_area[warp] = area; }
    __syncthreads();
    if (tid == 0) {
        float tsum = 0.0f; int tarea = 0;
#pragma unroll
        for (int k = 0; k < 8; k++) { tsum += s_sum[k]; tarea += s_area[k]; }
        g_part8[n * NCHUNK + c] = tsum;        // single writer: deterministic
        atomicAdd(&g_area[n], tarea);          // int atomic: deterministic
    }
}

// ============================================================
// Kernel 2: fused pair enumeration + popcount intersection.
// Grid-stride warps over all (i,j) cells; cheap smem label gate.
// ============================================================
__global__ __launch_bounds__(256) void popc_kernel(const int* __restrict__ labels)
{
    __shared__ int s_lab[NN];
    const int tid  = threadIdx.x;
    const int lane = tid & 31;
    const int gwarp = (blockIdx.x * 256 + tid) >> 5;
    const int NW = gridDim.x * 8;

    for (int k = tid; k < NN; k += 256) s_lab[k] = labels[k];
    __syncthreads();

    for (int p = gwarp; p < NN * NN; p += NW) {
        const int i = p / NN;
        const int j = p - i * NN;
        if (j <= i) continue;
        if (s_lab[i] != s_lab[j]) continue;

        const uint4* __restrict__ bi = reinterpret_cast<const uint4*>(g_bits + i * WSTRIDE);
        const uint4* __restrict__ bj = reinterpret_cast<const uint4*>(g_bits + j * WSTRIDE);

        int inter = 0;
#pragma unroll 5
        for (int w = lane; w < WSTRIDE / 4; w += 32) {   // 15 iterations
            uint4 a = bi[w];
            uint4 b = bj[w];
            inter += __popc(a.x & b.x) + __popc(a.y & b.y)
                   + __popc(a.z & b.z) + __popc(a.w & b.w);
        }
#pragma unroll
        for (int off = 16; off > 0; off >>= 1)
            inter += __shfl_down_sync(0xffffffffu, inter, off);

        if (lane == 0) {
            float uni = (float)(g_area[i] + g_area[j] - inter);
            float iou = (float)inter / fmaxf(uni, 1e-6f);
            atomicMax(reinterpret_cast<int*>(&g_comp[j]), __float_as_int(iou)); // iou>=0
            int pos = atomicAdd(&g_npairs, 1);
            g_pair_ij[pos] = ((unsigned)i << 16) | (unsigned)j;
            g_pair_d[pos] = iou;
        }
    }
}

// ============================================================
// Kernel 3 (single block, tiny data): scores + decay + output + reset.
// ============================================================
__global__ __launch_bounds__(1024) void decayfinal_kernel(
    const float* __restrict__ cate_scores,
    float* __restrict__ out)
{
    __shared__ float s_coef[NN];
    __shared__ float s_score[NN];
    const int tid = threadIdx.x;

    // phase 1: fixed-order reduce of 8 chunk partials per mask
    for (int n = tid; n < NN; n += 1024) {
        float acc = 0.0f;
#pragma unroll
        for (int k = 0; k < NCHUNK; k++) acc += g_part8[n * NCHUNK + k];
        float area = (float)g_area[n];
        s_score[n] = cate_scores[n] * (acc / fmaxf(area, 1.0f));
        s_coef[n] = 1.0f;
    }
    __syncthreads();

    // phase 2: decay terms -> order-independent min into smem coef
    const int np = g_npairs;
    for (int p = tid; p < np; p += 1024) {
        const unsigned ij = g_pair_ij[p];
        const int i = (int)(ij >> 16);
        const int j = (int)(ij & 0xffffu);
        const float d = g_pair_d[p];
        const float c = g_comp[i];
        const float term = __expf(SIGMA * (c * c - d * d));   // > 0
        atomicMin(reinterpret_cast<int*>(&s_coef[j]), __float_as_int(term));
    }
    __syncthreads();

    // phase 3: output + reset accumulators for next replay
    for (int n = tid; n < NN; n += 1024) {
        out[n] = s_score[n] * fminf(s_coef[n], 1.0f);
        g_area[n] = 0;
        g_comp[n] = 0.0f;
    }
    if (tid == 0) g_npairs = 0;
}

extern "C" void kernel_launch(void* const* d_in, const int* in_sizes, int n_in,
                              void* d_out, int out_size)
{
    const float* cate_scores = (const float*)d_in[0];
    const float* segx        = (const float*)d_in[1];
    const float* segy        = (const float*)d_in[2];
    const int*   labels      = (const int*)d_in[3];
    const int*   x_inds      = (const int*)d_in[4];
    const int*   y_inds      = (const int*)d_in[5];
    float* out = (float*)d_out;

    decode_kernel<<<NN * NCHUNK, 256>>>(segx, segy, x_inds, y_inds);
    popc_kernel<<<304, 256>>>(labels);
    decayfinal_kernel<<<1, 1024>>>(cate_scores, out);
}

// round 7
// speedup vs baseline: 2.2894x; 1.0875x over previous
#include <cuda_runtime.h>
#include <cstdint>

#define NN 500
#define GG 128
#define HH 200
#define WW 304
#define HWPX (HH * WW)            // 60800
#define WORDS 1900                // HWPX/32 exact
#define WSTRIDE 1920              // padded bit-row stride (u32), 16B multiple
#define MAXPAIRS (NN * (NN - 1) / 2)
#define MASK_THR 0.005f
#define SIGMA 2.0f

#define NCHUNK 8                  // chunks per mask
#define CHUNKW 240                // words per chunk (last: 220). multiple of 4.

// ---- device scratch (zero-init at load; decayfinal resets per replay) ----
__device__ __align__(16) unsigned int g_bits[NN * WSTRIDE];
__device__ float g_areaf[NN];             // exact small-int float sums: order-invariant
__device__ float g_part8[NN * NCHUNK];    // per-(mask,chunk) soft sums, single writer
__device__ float g_comp[NN];              // comp_iou (0 at entry)
__device__ int   g_npairs;                // 0 at entry
__device__ unsigned int g_pair_ij[MAXPAIRS];
__device__ float g_pair_d[MAXPAIRS];

// ============================================================
// Kernel 1: decode, warp-coalesced + issue-slimmed.
// Warp iteration = 128 consecutive pixels (lane L loads float4 #L).
// Bits packed in ballot order (fixed pixel permutation: invariant
// for AND/popc/area/sums). Area counted as predicated FADDs (FMA
// pipe), bits stored as one lane-0 STG.128.
// blockIdx.x = mask*8 + chunk.
// ============================================================
__global__ __launch_bounds__(256) void decode_kernel(
    const float* __restrict__ segx,
    const float* __restrict__ segy,
    const int* __restrict__ x_inds,
    const int* __restrict__ y_inds)
{
    const int n    = blockIdx.x >> 3;
    const int c    = blockIdx.x & 7;
    const int tid  = threadIdx.x;
    const int warp = tid >> 5;
    const int lane = tid & 31;

    const int xi = x_inds[n];
    const int yi = y_inds[n];
    const float4* __restrict__ rx = reinterpret_cast<const float4*>(segx + (size_t)xi * HWPX);
    const float4* __restrict__ ry = reinterpret_cast<const float4*>(segy + (size_t)yi * HWPX);

    const int w0 = c * CHUNKW;
    const int nquads = ((c == NCHUNK - 1) ? (WORDS - w0) : CHUNKW) >> 2;   // 60 or 55

    float ssum  = 0.0f;
    float areaf = 0.0f;

    const float4* pa = rx + (size_t)w0 * 8 + warp * 32 + lane;
    const float4* pb = ry + (size_t)w0 * 8 + warp * 32 + lane;
    uint4* pw = reinterpret_cast<uint4*>(g_bits + n * WSTRIDE + w0) + warp;

    for (int k = warp; k < nquads; k += 8, pa += 256, pb += 256, pw += 8) {
        const float4 a = *pa;
        const float4 b = *pb;
        const float s0 = a.x * b.x;
        const float s1 = a.y * b.y;
        const float s2 = a.z * b.z;
        const float s3 = a.w * b.w;
        const bool p0 = s0 > MASK_THR;
        const bool p1 = s1 > MASK_THR;
        const bool p2 = s2 > MASK_THR;
        const bool p3 = s3 > MASK_THR;
        const unsigned b0 = __ballot_sync(0xffffffffu, p0);
        const unsigned b1 = __ballot_sync(0xffffffffu, p1);
        const unsigned b2 = __ballot_sync(0xffffffffu, p2);
        const unsigned b3 = __ballot_sync(0xffffffffu, p3);
        if (p0) { ssum += s0; areaf += 1.0f; }
        if (p1) { ssum += s1; areaf += 1.0f; }
        if (p2) { ssum += s2; areaf += 1.0f; }
        if (p3) { ssum += s3; areaf += 1.0f; }
        if (lane == 0)
            *pw = make_uint4(b0, b1, b2, b3);
    }
    // last chunk zeroes the pad words [1900,1920)
    if (c == NCHUNK - 1 && tid < WSTRIDE - WORDS)
        g_bits[n * WSTRIDE + WORDS + tid] = 0u;

    // block reduction (8 warps, two floats)
    __shared__ float s_sum[8];
    __shared__ float s_area[8];
#pragma unroll
    for (int off = 16; off > 0; off >>= 1) {
        ssum  += __shfl_down_sync(0xffffffffu, ssum,  off);
        areaf += __shfl_down_sync(0xffffffffu, areaf, off);
    }
    if (lane == 0) { s_sum[warp] = ssum; s_area[warp] = areaf; }
    __syncthreads();
    if (tid == 0) {
        float tsum = 0.0f, tarea = 0.0f;
#pragma unroll
        for (int k = 0; k < 8; k++) { tsum += s_sum[k]; tarea += s_area[k]; }
        g_part8[n * NCHUNK + c] = tsum;      // single writer: deterministic
        atomicAdd(&g_areaf[n], tarea);       // exact int-valued float: order-invariant
    }
}

// ============================================================
// Kernel 2: fused pair enumeration + popcount intersection.
// ============================================================
__global__ __launch_bounds__(256) void popc_kernel(const int* __restrict__ labels)
{
    __shared__ int s_lab[NN];
    const int tid  = threadIdx.x;
    const int lane = tid & 31;
    const int gwarp = (blockIdx.x * 256 + tid) >> 5;
    const int NW = gridDim.x * 8;

    for (int k = tid; k < NN; k += 256) s_lab[k] = labels[k];
    __syncthreads();

    for (int p = gwarp; p < NN * NN; p += NW) {
        const int i = p / NN;
        const int j = p - i * NN;
        if (j <= i) continue;
        if (s_lab[i] != s_lab[j]) continue;

        const uint4* __restrict__ bi = reinterpret_cast<const uint4*>(g_bits + i * WSTRIDE);
        const uint4* __restrict__ bj = reinterpret_cast<const uint4*>(g_bits + j * WSTRIDE);

        int inter = 0;
#pragma unroll 5
        for (int w = lane; w < WSTRIDE / 4; w += 32) {   // 15 iterations
            uint4 a = bi[w];
            uint4 b = bj[w];
            inter += __popc(a.x & b.x) + __popc(a.y & b.y)
                   + __popc(a.z & b.z) + __popc(a.w & b.w);
        }
#pragma unroll
        for (int off = 16; off > 0; off >>= 1)
            inter += __shfl_down_sync(0xffffffffu, inter, off);

        if (lane == 0) {
            float uni = g_areaf[i] + g_areaf[j] - (float)inter;
            float iou = (float)inter / fmaxf(uni, 1e-6f);
            atomicMax(reinterpret_cast<int*>(&g_comp[j]), __float_as_int(iou)); // iou>=0
            int pos = atomicAdd(&g_npairs, 1);
            g_pair_ij[pos] = ((unsigned)i << 16) | (unsigned)j;
            g_pair_d[pos] = iou;
        }
    }
}

// ============================================================
// Kernel 3 (single block, tiny data): scores + decay + output + reset.
// ============================================================
__global__ __launch_bounds__(1024) void decayfinal_kernel(
    const float* __restrict__ cate_scores,
    float* __restrict__ out)
{
    __shared__ float s_coef[NN];
    __shared__ float s_score[NN];
    const int tid = threadIdx.x;

    // phase 1: fixed-order reduce of 8 chunk partials per mask
    for (int n = tid; n < NN; n += 1024) {
        float acc = 0.0f;
#pragma unroll
        for (int k = 0; k < NCHUNK; k++) acc += g_part8[n * NCHUNK + k];
        s_score[n] = cate_scores[n] * (acc / fmaxf(g_areaf[n], 1.0f));
        s_coef[n] = 1.0f;
    }
    __syncthreads();

    // phase 2: decay terms -> order-independent min into smem coef
    const int np = g_npairs;
    for (int p = tid; p < np; p += 1024) {
        const unsigned ij = g_pair_ij[p];
        const int i = (int)(ij >> 16);
        const int j = (int)(ij & 0xffffu);
        const float d = g_pair_d[p];
        const float c = g_comp[i];
        const float term = __expf(SIGMA * (c * c - d * d));   // > 0
        atomicMin(reinterpret_cast<int*>(&s_coef[j]), __float_as_int(term));
    }
    __syncthreads();

    // phase 3: output + reset accumulators for next replay
    for (int n = tid; n < NN; n += 1024) {
        out[n] = s_score[n] * fminf(s_coef[n], 1.0f);
        g_areaf[n] = 0.0f;
        g_comp[n] = 0.0f;
    }
    if (tid == 0) g_npairs = 0;
}

extern "C" void kernel_launch(void* const* d_in, const int* in_sizes, int n_in,
                              void* d_out, int out_size)
{
    const float* cate_scores = (const float*)d_in[0];
    const float* segx        = (const float*)d_in[1];
    const float* segy        = (const float*)d_in[2];
    const int*   labels      = (const int*)d_in[3];
    const int*   x_inds      = (const int*)d_in[4];
    const int*   y_inds      = (const int*)d_in[5];
    float* out = (float*)d_out;

    decode_kernel<<<NN * NCHUNK, 256>>>(segx, segy, x_inds, y_inds);
    popc_kernel<<<304, 256>>>(labels);
    decayfinal_kernel<<<1, 1024>>>(cate_scores, out);
}